// round 7
// baseline (speedup 1.0000x reference)
#include <cuda_runtime.h>
#include <math.h>

// Scratch: Q1 ping-pong in both layouts + transposed mask. [B,S,S], B=4,S=160 -> 102400
#define MAXQ 102400
__device__ float g_q1 [2][MAXQ];   // Q1[b,m,h]   (row layout)
__device__ float g_q1T[2][MAXQ];   // Q1[b,h,m]   (transposed)
__device__ float g_mt [MAXQ];      // m_t[b,h,t] = (mask[b,t,h] && t!=h) ? 1 : 0

// Pre-pass: transpose mask into [b,h,t] float layout with t!=h folded in.
__global__ void mask_transpose_kernel(const int* __restrict__ mask, int S)
{
    int t = threadIdx.x;
    int h = blockIdx.x % S;
    int b = blockIdx.x / S;
    if (t < S) {
        int v = mask[(b * S + t) * S + h];
        g_mt[(b * S + h) * S + t] = (v != 0 && t != h) ? 1.f : 0.f;
    }
}

// MODE 0: iter 1, Q1 == 0.5 (no Q1 reads). MODE 1: middle iter. MODE 2: final -> output.
template<int MODE>
__global__ void __launch_bounds__(256, 4)
mfvi_kernel(const float* __restrict__ se,
            const float* __restrict__ ss,
            const float* __restrict__ sc,
            const float* __restrict__ sg,
            const int* __restrict__ mask,
            float* __restrict__ out,
            int S, int parity)
{
    const int RW = 4;                      // h-rows per warp (one per 8-lane group)
    const int ROWS = 8 * RW;               // 32 h-rows per block (8 warps)
    int ntile = (S + ROWS - 1) / ROWS;
    int blk = blockIdx.x;
    int htile = blk % ntile;
    int m     = (blk / ntile) % S;
    int b     = blk / (ntile * S);
    int warp = threadIdx.x >> 5;
    int lane = threadIdx.x & 31;
    int g    = lane >> 3;                  // group (row) index 0..3
    int li   = lane & 7;                   // lane within group
    int h0b  = htile * ROWS;               // first h-row of this block
    int h    = h0b + warp * RW + g;        // this thread's h-row
    int rt   = warp * RW + g;              // row within tile

    int FV = S >> 2;                       // float4 per row (40 for S=160)

    extern __shared__ float smbuf[];
    float* sm_row = smbuf;                 // Q1[b,m,t]          [S]
    float* sm_col = smbuf + S;             // Q1[b,t,m]          [S]
    float* sm_mt  = smbuf + 2 * S;         // mt rows            [ROWS*S]
    float* sm_mqa = sm_mt + ROWS * S;      // mt*q1T rows        [ROWS*S]

    const float* __restrict__ q1_in  = g_q1 [parity & 1];
    const float* __restrict__ q1T_in = g_q1T[parity & 1];

    // ---- stage mt (and mt*qa) rows for this block's 32 h values ----
    {
        long hbase0 = ((long)(b * S + h0b)) * S;
        const float4* mt4 = (const float4*)(g_mt + hbase0);
        const float4* qa4 = (const float4*)(q1T_in + hbase0);
        int NV = ROWS * FV;                // 1280 float4
        if (MODE == 0) {
            for (int i = threadIdx.x; i < NV; i += blockDim.x) {
                float4 mv = mt4[i];
                mv.x *= 0.5f; mv.y *= 0.5f; mv.z *= 0.5f; mv.w *= 0.5f;
                ((float4*)sm_mt)[i] = mv;  // 0.5 folded for MODE 0
            }
        } else {
            for (int i = threadIdx.x; i < NV; i += blockDim.x) {
                float4 mv = mt4[i];
                float4 qv = qa4[i];
                ((float4*)sm_mt)[i] = mv;
                qv.x *= mv.x; qv.y *= mv.y; qv.z *= mv.z; qv.w *= mv.w;
                ((float4*)sm_mqa)[i] = qv;
            }
            int nv = FV;
            const float4* r4 = (const float4*)(q1_in  + (b * S + m) * S);
            const float4* c4 = (const float4*)(q1T_in + (b * S + m) * S);
            for (int i = threadIdx.x; i < 2 * nv; i += blockDim.x) {
                if (i < nv) ((float4*)sm_row)[i] = r4[i];
                else        ((float4*)sm_col)[i - nv] = c4[i - nv];
            }
        }
        __syncthreads();
    }

    bool valid = (h < S);
    const long sbase = (((long)(b * S + m)) * S + h) * S;
    const float4* p_ss = (const float4*)(ss + sbase);
    const float4* p_sc = (const float4*)(sc + sbase);
    const float4* p_sg = (const float4*)(sg + sbase);
    const float4* smt  = ((const float4*)sm_mt)  + rt * FV;
    const float4* smqa = ((const float4*)sm_mqa) + rt * FV;
    const float4* srow = (const float4*)sm_row;
    const float4* scol = (const float4*)sm_col;

    // Full sum over t (t==m term subtracted after reduction)
    float acc = 0.f;
    if (valid) {
        #pragma unroll 5
        for (int v = li; v < FV; v += 8) {
            float4 vss = p_ss[v];
            float4 vsc = p_sc[v];
            float4 vsg = p_sg[v];
            float4 vmt = smt[v];
            if (MODE == 0) {
                #pragma unroll
                for (int j = 0; j < 4; j++)
                    acc += (&vmt.x)[j] * ((&vss.x)[j] + (&vsc.x)[j] + (&vsg.x)[j]);
            } else {
                float4 vmq = smqa[v];
                float4 vr  = srow[v];
                float4 vc  = scol[v];
                #pragma unroll
                for (int j = 0; j < 4; j++) {
                    float c2 = (&vsc.x)[j] * (&vr.x)[j] + (&vsg.x)[j] * (&vc.x)[j];
                    acc += (&vss.x)[j] * (&vmq.x)[j] + (&vmt.x)[j] * c2;
                }
            }
        }
    }

    // reduce within the 8-lane group
    acc += __shfl_down_sync(0xffffffffu, acc, 4, 8);
    acc += __shfl_down_sync(0xffffffffu, acc, 2, 8);
    acc += __shfl_down_sync(0xffffffffu, acc, 1, 8);

    if (li == 0 && valid) {
        // subtract the t == m term (mt already folds mask & t!=h; MODE0 has 0.5 folded)
        float corr;
        if (MODE == 0) {
            corr = sm_mt[rt * S + m] * (ss[sbase + m] + sc[sbase + m] + sg[sbase + m]);
        } else {
            corr = ss[sbase + m] * sm_mqa[rt * S + m]
                 + sm_mt[rt * S + m] * (sc[sbase + m] * sm_row[m]
                                      + sg[sbase + m] * sm_col[m]);
        }
        acc -= corr;

        int idx = (b * S + m) * S + h;
        float f = (mask[idx] != 0) ? acc : 0.f;
        float q = se[idx] + f;
        if (MODE == 2) {
            out[(long)idx * 2 + 0] = 1.f / (1.f + expf(q));
            out[(long)idx * 2 + 1] = 1.f / (1.f + expf(-q));
        } else {
            float q1v = 1.f / (1.f + expf(-q));
            int ob = (parity ^ 1) & 1;
            g_q1 [ob][idx] = q1v;
            g_q1T[ob][(b * S + h) * S + m] = q1v;
        }
    }
}

extern "C" void kernel_launch(void* const* d_in, const int* in_sizes, int n_in,
                              void* d_out, int out_size)
{
    const float* se = (const float*)d_in[0];
    const float* ss = (const float*)d_in[1];
    const float* sc = (const float*)d_in[2];
    const float* sg = (const float*)d_in[3];
    const int* mask = (const int*)d_in[4];
    float* out = (float*)d_out;

    int BSS = in_sizes[0];                  // B*S*S
    int S = in_sizes[1] / BSS;              // (B*S^3)/(B*S^2)
    int B = BSS / (S * S);

    mask_transpose_kernel<<<B * S, (S + 31) & ~31>>>(mask, S);

    const int ROWS = 32;
    int ntile = (S + ROWS - 1) / ROWS;
    dim3 grid(B * S * ntile);
    size_t smem = (2 * (size_t)S + 2 * (size_t)ROWS * S) * sizeof(float); // 42.2KB

    mfvi_kernel<0><<<grid, 256, smem>>>(se, ss, sc, sg, mask, out, S, 1);
    mfvi_kernel<1><<<grid, 256, smem>>>(se, ss, sc, sg, mask, out, S, 0);
    mfvi_kernel<2><<<grid, 256, smem>>>(se, ss, sc, sg, mask, out, S, 1);
}

// round 8
// speedup vs baseline: 1.0773x; 1.0773x over previous
#include <cuda_runtime.h>
#include <math.h>

// Scratch: Q1 ping-pong in both layouts. [B,S,S], B=4,S=160 -> 102400
#define MAXQ 102400
#define MAXR 1024                  // max B*S rows
__device__ float g_q1 [2][MAXQ];   // Q1[b,m,h]   (row layout)
__device__ float g_q1T[2][MAXQ];   // Q1[b,h,m]   (transposed)
__device__ int   g_excl[MAXQ];     // per (b,h): excluded t list (mask[b,t,h]==0 || t==h)
__device__ int   g_ecnt[MAXR];     // per (b,h): list length

// Pre-pass: build per-(b,h) exclusion list.
__global__ void excl_build_kernel(const int* __restrict__ mask, int S)
{
    __shared__ int cnt;
    int t = threadIdx.x;
    int h = blockIdx.x % S;
    int b = blockIdx.x / S;
    int row = b * S + h;
    if (t == 0) cnt = 0;
    __syncthreads();
    if (t < S) {
        bool ex = (mask[(b * S + t) * S + h] == 0) || (t == h);
        if (ex) {
            int slot = atomicAdd(&cnt, 1);
            g_excl[row * S + slot] = t;
        }
    }
    __syncthreads();
    if (t == 0) g_ecnt[row] = cnt;
}

// MODE 0: iter 1, Q1 == 0.5 (no Q1 reads). MODE 1: middle iter. MODE 2: final -> output.
template<int MODE>
__global__ void __launch_bounds__(256, 4)
mfvi_kernel(const float* __restrict__ se,
            const float* __restrict__ ss,
            const float* __restrict__ sc,
            const float* __restrict__ sg,
            const int* __restrict__ mask,
            float* __restrict__ out,
            int S, int parity)
{
    const int RW = 4;                      // h-rows per warp (one per 8-lane group)
    const int HT = 8 * RW;                 // 32 h per block (8 warps)
    int ntile = (S + HT - 1) / HT;
    int blk = blockIdx.x;
    int htile = blk % ntile;
    int m     = (blk / ntile) % S;
    int b     = blk / (ntile * S);
    int warp = threadIdx.x >> 5;
    int lane = threadIdx.x & 31;
    int g    = lane >> 3;                  // group (row) index 0..3
    int li   = lane & 7;                   // lane within group
    int h    = htile * HT + warp * RW + g; // this thread's h-row

    extern __shared__ float smbuf[];
    float* sm_row = smbuf;        // Q1[b,m,t]  = q1 [(b,m),t]  contiguous
    float* sm_col = smbuf + S;    // Q1[b,t,m]  = q1T[(b,m),t]  contiguous

    const float* __restrict__ q1_in  = g_q1 [parity & 1];
    const float* __restrict__ q1T_in = g_q1T[parity & 1];

    if (MODE != 0) {
        int nv = S >> 2;
        const float4* r4 = (const float4*)(q1_in  + (b * S + m) * S);
        const float4* c4 = (const float4*)(q1T_in + (b * S + m) * S);
        for (int i = threadIdx.x; i < 2 * nv; i += blockDim.x) {
            if (i < nv) ((float4*)sm_row)[i] = r4[i];
            else        ((float4*)sm_col)[i - nv] = c4[i - nv];
        }
        __syncthreads();
    }

    bool valid = (h < S);
    int FV = S >> 2;                       // float4 per row (40 for S=160)

    const long sbase = (((long)(b * S + m)) * S + h) * S;
    const long hbase = ((long)(b * S + h)) * S;
    const float4* p_ss = (const float4*)(ss + sbase);
    const float4* p_sc = (const float4*)(sc + sbase);
    const float4* p_sg = (const float4*)(sg + sbase);
    const float4* p_qa = (const float4*)(q1T_in + hbase);
    const float4* srow = (const float4*)sm_row;
    const float4* scol = (const float4*)sm_col;

    // Unmasked full sum over t; exclusions subtracted afterward.
    float acc = 0.f;
    if (valid) {
        #pragma unroll 5
        for (int v = li; v < FV; v += 8) {
            float4 vss = __ldcs(p_ss + v);
            float4 vsc = __ldcs(p_sc + v);
            float4 vsg = __ldcs(p_sg + v);
            if (MODE == 0) {
                #pragma unroll
                for (int j = 0; j < 4; j++)
                    acc += (&vss.x)[j] + (&vsc.x)[j] + (&vsg.x)[j];
            } else {
                float4 vqa = p_qa[v];
                float4 vr  = srow[v];
                float4 vc  = scol[v];
                #pragma unroll
                for (int j = 0; j < 4; j++) {
                    acc += (&vss.x)[j] * (&vqa.x)[j];
                    acc += (&vsc.x)[j] * (&vr.x)[j];
                    acc += (&vsg.x)[j] * (&vc.x)[j];
                }
            }
        }
    }

    // reduce within the 8-lane group
    acc += __shfl_down_sync(0xffffffffu, acc, 4, 8);
    acc += __shfl_down_sync(0xffffffffu, acc, 2, 8);
    acc += __shfl_down_sync(0xffffffffu, acc, 1, 8);

    if (li == 0 && valid) {
        int idx = (b * S + m) * S + h;
        float f = 0.f;
        if (mask[idx] != 0) {
            if (MODE == 0) acc *= 0.5f;
            // subtract excluded-t terms (mask[b,t,h]==0 or t==h)
            int row = b * S + h;
            int cnt = g_ecnt[row];
            for (int i = 0; i < cnt; i++) {
                int t = g_excl[row * S + i];
                if (MODE == 0)
                    acc -= 0.5f * (ss[sbase + t] + sc[sbase + t] + sg[sbase + t]);
                else
                    acc -= ss[sbase + t] * q1T_in[hbase + t]
                         + sc[sbase + t] * sm_row[t]
                         + sg[sbase + t] * sm_col[t];
            }
            // subtract t == m term (m is in the list only when m==h, given mask[idx]!=0)
            if (m != h) {
                if (MODE == 0)
                    acc -= 0.5f * (ss[sbase + m] + sc[sbase + m] + sg[sbase + m]);
                else
                    acc -= ss[sbase + m] * q1T_in[hbase + m]
                         + sc[sbase + m] * sm_row[m]
                         + sg[sbase + m] * sm_col[m];
            }
            f = acc;
        }
        float q = se[idx] + f;
        if (MODE == 2) {
            out[(long)idx * 2 + 0] = 1.f / (1.f + expf(q));
            out[(long)idx * 2 + 1] = 1.f / (1.f + expf(-q));
        } else {
            float q1v = 1.f / (1.f + expf(-q));
            int ob = (parity ^ 1) & 1;
            g_q1 [ob][idx] = q1v;
            g_q1T[ob][(b * S + h) * S + m] = q1v;
        }
    }
}

extern "C" void kernel_launch(void* const* d_in, const int* in_sizes, int n_in,
                              void* d_out, int out_size)
{
    const float* se = (const float*)d_in[0];
    const float* ss = (const float*)d_in[1];
    const float* sc = (const float*)d_in[2];
    const float* sg = (const float*)d_in[3];
    const int* mask = (const int*)d_in[4];
    float* out = (float*)d_out;

    int BSS = in_sizes[0];                  // B*S*S
    int S = in_sizes[1] / BSS;              // (B*S^3)/(B*S^2)
    int B = BSS / (S * S);

    excl_build_kernel<<<B * S, (S + 31) & ~31>>>(mask, S);

    int ntile = (S + 31) / 32;              // 32 h per block
    dim3 grid(B * S * ntile);
    size_t smem = 2 * (size_t)S * sizeof(float);

    mfvi_kernel<0><<<grid, 256, smem>>>(se, ss, sc, sg, mask, out, S, 1);
    mfvi_kernel<1><<<grid, 256, smem>>>(se, ss, sc, sg, mask, out, S, 0);
    mfvi_kernel<2><<<grid, 256, smem>>>(se, ss, sc, sg, mask, out, S, 1);
}